// round 13
// baseline (speedup 1.0000x reference)
#include <cuda_runtime.h>
#include <cuda_bf16.h>
#include <cuda_fp16.h>
#include <cstdint>

#define BB  8
#define QQ  32
#define LEN 128
#define DD  512
#define PP  32
#define AA  128
#define NBQ (BB*QQ)

// Scratch (device globals: allocation-free, graph-capturable)
__device__ float g_ws[BB*PP*AA];                 // (B,P,A)
__device__ float g_uhc[BB*QQ*LEN*AA];            // compacted uh rows (dense) 16MB
__device__ float g_e [BB*PP*QQ*LEN];             // (B,P,Q,LE) raw scores, 4 MB
__device__ float g_mx[BB*PP];                    // softmax row max
__device__ float g_inv[BB*PP];                   // softmax 1/sum
__device__ __half g_Uh[AA*DD];                   // U hi split (fp16)
__device__ __half g_Ul[AA*DD];                   // U lo split (fp16)
__device__ __half g_Xh[(NBQ*LEN + 64)*DD];       // compacted X rows fp16 (32MB)
__device__ int   g_cnt[NBQ];                     // unmasked count per (b,q)
__device__ int   g_off[NBQ+1];                   // exclusive offsets
__device__ int   g_tloc[NBQ*LEN];                // per-bq local compacted t
__device__ int   g_tidx[NBQ*LEN + 128];          // dense flat rows (bq*128+t), padded
__device__ int   g_nblk[1];                      // #128-row blocks

// ---------------------------------------------------------------------------
// helpers
// ---------------------------------------------------------------------------
__device__ __forceinline__ float tanh_fast(float x){
    float y; asm("tanh.approx.f32 %0, %1;" : "=f"(y) : "f"(x)); return y;
}
__device__ __forceinline__ uint32_t smem_u32(const void* p){
    uint32_t a;
    asm("{ .reg .u64 t; cvta.to.shared.u64 t, %1; cvt.u32.u64 %0, t; }" : "=r"(a) : "l"(p));
    return a;
}
__device__ __forceinline__ uint32_t h2u(__half2 v){
    return *reinterpret_cast<uint32_t*>(&v);
}
// sm_80+ primitives (valid at target sm_103)
__device__ __forceinline__ void ldsm4(uint32_t* r, uint32_t a){
    asm volatile("ldmatrix.sync.aligned.m8n8.x4.shared.b16 {%0,%1,%2,%3}, [%4];"
        : "=r"(r[0]), "=r"(r[1]), "=r"(r[2]), "=r"(r[3]) : "r"(a));
}
__device__ __forceinline__ void ldsm4t(uint32_t* r, uint32_t a){
    asm volatile("ldmatrix.sync.aligned.m8n8.x4.trans.shared.b16 {%0,%1,%2,%3}, [%4];"
        : "=r"(r[0]), "=r"(r[1]), "=r"(r[2]), "=r"(r[3]) : "r"(a));
}
__device__ __forceinline__ void mma_f16(float* c, const uint32_t* a, const uint32_t* b){
    asm volatile("mma.sync.aligned.m16n8k16.row.col.f32.f16.f16.f32 "
        "{%0,%1,%2,%3}, {%4,%5,%6,%7}, {%8,%9}, {%0,%1,%2,%3};"
        : "+f"(c[0]), "+f"(c[1]), "+f"(c[2]), "+f"(c[3])
        : "r"(a[0]), "r"(a[1]), "r"(a[2]), "r"(a[3]), "r"(b[0]), "r"(b[1]));
}
__device__ __forceinline__ void cp16(uint32_t d, const void* s){
    asm volatile("cp.async.cg.shared.global [%0], [%1], 16;" :: "r"(d), "l"(s));
}
#define CP_COMMIT() asm volatile("cp.async.commit_group;" ::: "memory")
#define CP_WAIT0()  asm volatile("cp.async.wait_group 0;" ::: "memory")

// ---------------------------------------------------------------------------
// K_SETUP (fused): blocks 0..63 -> ws (4 bp rows each); 64..319 -> compact1;
//                  320..383 -> prep_u
// ---------------------------------------------------------------------------
__global__ void __launch_bounds__(256) k_setup(const float* __restrict__ s_j,
                                               const float* __restrict__ Ws_w,
                                               const float* __restrict__ Ws_b,
                                               const float* __restrict__ U,
                                               const int*   __restrict__ exp_mask){
    const int blk = blockIdx.x;
    const int tid = threadIdx.x;
    if (blk < 64){
        __shared__ float sj[4][DD];
        const int bp0 = blk * 4;
        #pragma unroll
        for (int i = 0; i < 2; i++){
            int idx = tid + i*256;
            int rr = idx >> 7, c4 = (idx & 127) * 4;
            *(float4*)&sj[rr][c4] = *(const float4*)(s_j + (size_t)(bp0+rr)*DD + c4);
        }
        __syncthreads();
        const int a = tid & 127, half = tid >> 7;
        float acc0 = 0.0f, acc1 = 0.0f;
        const float* wr = Ws_w + (size_t)a*DD;
        const float* s0 = sj[half*2 + 0];
        const float* s1 = sj[half*2 + 1];
        #pragma unroll 8
        for (int d = 0; d < DD; d += 4){
            float4 w = *(const float4*)(wr + d);
            float4 x0 = *(const float4*)(s0 + d);
            float4 x1 = *(const float4*)(s1 + d);
            acc0 += w.x*x0.x + w.y*x0.y + w.z*x0.z + w.w*x0.w;
            acc1 += w.x*x1.x + w.y*x1.y + w.z*x1.z + w.w*x1.w;
        }
        float bb = Ws_b[a];
        g_ws[(bp0 + half*2 + 0)*AA + a] = acc0 + bb;
        g_ws[(bp0 + half*2 + 1)*AA + a] = acc1 + bb;
    } else if (blk < 320){
        __shared__ int wc[4];
        const int bq = blk - 64;
        const int lane = tid & 31, w = tid >> 5;
        bool m = false; unsigned bal = 0;
        if (tid < 128){
            m = exp_mask[bq*LEN + tid] != 0;
            bal = __ballot_sync(0xffffffffu, m);
            if (lane == 0) wc[w] = __popc(bal);
        }
        __syncthreads();
        if (tid < 128){
            int base = 0;
            #pragma unroll
            for (int i = 0; i < 4; i++) if (i < w) base += wc[i];
            int pre = __popc(bal & ((1u << lane) - 1u));
            if (m) g_tloc[bq*LEN + base + pre] = tid;
            if (tid == 0) g_cnt[bq] = wc[0] + wc[1] + wc[2] + wc[3];
        }
    } else {
        int idx = ((blk - 320) * 256 + tid) * 4;
        float4 v = *(const float4*)(U + idx);
        __half hx = __float2half(v.x), hy = __float2half(v.y);
        __half hz = __float2half(v.z), hw = __float2half(v.w);
        __half2 h01 = __halves2half2(hx, hy);
        __half2 h23 = __halves2half2(hz, hw);
        __half2 l01 = __floats2half2_rn(v.x - __half2float(hx), v.y - __half2float(hy));
        __half2 l23 = __floats2half2_rn(v.z - __half2float(hz), v.w - __half2float(hw));
        *(__half2*)(g_Uh + idx)     = h01;
        *(__half2*)(g_Uh + idx + 2) = h23;
        *(__half2*)(g_Ul + idx)     = l01;
        *(__half2*)(g_Ul + idx + 2) = l23;
    }
}

// ---------------------------------------------------------------------------
// K_COMPACT: fused scan + scatter. 256 blocks x 256 thr.
// ---------------------------------------------------------------------------
__global__ void __launch_bounds__(256) k_compact(){
    __shared__ int s[256];
    const int bq = blockIdx.x, tid = threadIdx.x;
    s[tid] = g_cnt[tid];
    __syncthreads();
    #pragma unroll
    for (int o = 1; o < 256; o <<= 1){
        int v = (tid >= o) ? s[tid - o] : 0;
        __syncthreads();
        s[tid] += v;
        __syncthreads();
    }
    const int off = (bq == 0) ? 0 : s[bq - 1];
    const int cnt = s[bq] - off;
    if (tid < cnt) g_tidx[off + tid] = bq*LEN + g_tloc[bq*LEN + tid];
    if (tid == 0){ g_off[bq + 1] = s[bq]; if (bq == 0) g_off[0] = 0; }
    if (bq == 0){
        const int tot = s[255];
        const int pad = (tot + 127) & ~127;
        if (tid < pad - tot) g_tidx[tot + tid] = 0;
        if (tid == 0) g_nblk[0] = pad >> 7;
        uint4* z = (uint4*)(g_Xh + (size_t)tot * DD);
        #pragma unroll
        for (int i = 0; i < 8; i++) z[tid + i*256] = make_uint4(0,0,0,0);
    }
}

// ---------------------------------------------------------------------------
// K2: uh = gather(X) @ U^T, fp16 2-term, N-split CTAs (unchanged from R11).
// ---------------------------------------------------------------------------
#define XROWB 144
#define XTILEB (128*XROWB)
#define UTILEB (64*XROWB)
#define CHUNKB (XTILEB + 2*UTILEB)
#define UHMMA_SMEM (2*CHUNKB)              // 73728

__global__ void __launch_bounds__(512, 2) k_uh_mma(const float* __restrict__ X){
    const int bid = blockIdx.x;
    if (bid >= 2*g_nblk[0]) return;
    extern __shared__ char sm[];
    const uint32_t sb = smem_u32(sm);
    const int tid  = threadIdx.x;
    const int lane = tid & 31, wid = tid >> 5;
    const int warp_m = wid & 3;
    const int warp_n = wid >> 2;
    const int rb = bid >> 1, nh = bid & 1;
    const int m0 = rb * 128;
    const int ub = nh * 64;

    float acc[2][2][4];
    #pragma unroll
    for (int a = 0; a < 2; a++)
        #pragma unroll
        for (int b = 0; b < 2; b++)
            #pragma unroll
            for (int c = 0; c < 4; c++) acc[a][b][c] = 0.0f;

    const float* xp[4];
    uint32_t soff[4];
    #pragma unroll
    for (int j = 0; j < 4; j++){
        int idx = tid + j*512;
        int row = idx >> 4, k4 = (idx & 15) * 4;
        xp[j] = X + (size_t)g_tidx[m0 + row]*DD + k4;
        soff[j] = (uint32_t)row*XROWB + (uint32_t)k4*2;
    }
    const int urow = tid >> 3, useg = tid & 7;
    const uint32_t uoff = (uint32_t)urow*XROWB + useg*16;

    float4 xr[4];
    #pragma unroll
    for (int j = 0; j < 4; j++) xr[j] = *(const float4*)(xp[j]);
    cp16(sb + XTILEB          + uoff, g_Uh + (size_t)(ub + urow)*DD + useg*8);
    cp16(sb + XTILEB + UTILEB + uoff, g_Ul + (size_t)(ub + urow)*DD + useg*8);
    CP_COMMIT();
    #pragma unroll
    for (int j = 0; j < 4; j++){
        int idx = tid + j*512;
        int row = idx >> 4, k4 = (idx & 15) * 4;
        float4 v = xr[j];
        uint2 h = make_uint2(h2u(__floats2half2_rn(v.x, v.y)),
                             h2u(__floats2half2_rn(v.z, v.w)));
        *(uint2*)(sm + soff[j]) = h;
        if (nh == 0) *(uint2*)(g_Xh + (size_t)(m0 + row)*DD + k4) = h;
    }
    CP_WAIT0();
    __syncthreads();

    const uint32_t a_base = (uint32_t)(warp_m*32 + (lane & 15))*XROWB + ((lane >> 4) << 4);
    const uint32_t b_base = (uint32_t)(warp_n*16 + (lane & 7) + ((lane >> 4) << 3))*XROWB
                          + (((lane >> 3) & 1) << 4);

    for (int c = 0; c < DD/64; c++){
        const uint32_t boff = (uint32_t)(c & 1) * CHUNKB;
        const uint32_t noff = boff ^ CHUNKB;
        const int k0n = (c+1) * 64;
        if (c < 7){
            #pragma unroll
            for (int j = 0; j < 4; j++) xr[j] = *(const float4*)(xp[j] + k0n);
            cp16(sb + noff + XTILEB          + uoff, g_Uh + (size_t)(ub + urow)*DD + k0n + useg*8);
            cp16(sb + noff + XTILEB + UTILEB + uoff, g_Ul + (size_t)(ub + urow)*DD + k0n + useg*8);
            CP_COMMIT();
        }
        const uint32_t xh = sb + boff;
        const uint32_t uh = xh + XTILEB, ul = uh + UTILEB;
        #pragma unroll
        for (int ks = 0; ks < 4; ks++){
            const uint32_t kb = (uint32_t)ks * 32;
            uint32_t ah[2][4];
            ldsm4(ah[0], xh + a_base + kb);
            ldsm4(ah[1], xh + a_base + kb + 16*XROWB);
            uint32_t t0[4], t1[4];
            ldsm4(t0, uh + b_base + kb);
            ldsm4(t1, ul + b_base + kb);
            uint32_t bh0[2] = {t0[0], t0[1]}, bh1[2] = {t0[2], t0[3]};
            uint32_t bl0[2] = {t1[0], t1[1]}, bl1[2] = {t1[2], t1[3]};
            #pragma unroll
            for (int mt = 0; mt < 2; mt++){
                mma_f16(acc[mt][0], ah[mt], bh0);
                mma_f16(acc[mt][0], ah[mt], bl0);
                mma_f16(acc[mt][1], ah[mt], bh1);
                mma_f16(acc[mt][1], ah[mt], bl1);
            }
        }
        if (c < 7){
            #pragma unroll
            for (int j = 0; j < 4; j++){
                int idx = tid + j*512;
                int row = idx >> 4, k4 = (idx & 15) * 4;
                float4 v = xr[j];
                uint2 h = make_uint2(h2u(__floats2half2_rn(v.x, v.y)),
                                     h2u(__floats2half2_rn(v.z, v.w)));
                *(uint2*)(sm + noff + soff[j]) = h;
                if (nh == 0) *(uint2*)(g_Xh + (size_t)(m0 + row)*DD + k0n + k4) = h;
            }
            CP_WAIT0();
        }
        __syncthreads();
    }

    const int r = lane >> 2, cp2 = (lane & 3) * 2;
    float* base = g_uhc + (size_t)(m0 + warp_m*32) * AA + ub + warp_n*16;
    #pragma unroll
    for (int mt = 0; mt < 2; mt++){
        #pragma unroll
        for (int nt = 0; nt < 2; nt++){
            float* p0 = base + (size_t)(mt*16 + r) * AA + nt*8 + cp2;
            float* p1 = base + (size_t)(mt*16 + r + 8) * AA + nt*8 + cp2;
            *(float2*)p0 = make_float2(acc[mt][nt][0], acc[mt][nt][1]);
            *(float2*)p1 = make_float2(acc[mt][nt][2], acc[mt][nt][3]);
        }
    }
}

// ---------------------------------------------------------------------------
// K3: e over compacted slots, T-CHUNKED: grid (Q, B, 2); blockIdx.z = t-half.
// Each block handles 64 slots -> uh_s 64 rows -> 51.9KB smem -> 4 CTAs/SM.
// Chunks write disjoint e entries (no reduction). th==0 also writes -1e9
// for ALL masked t. th==1 exits if cnt <= 64.
// ---------------------------------------------------------------------------
__global__ void __launch_bounds__(256, 4) k_score(const int*   __restrict__ exp_mask,
                                                  const float* __restrict__ v_w){
    extern __shared__ float smf[];
    float* uh_s = smf;                   // 64*132
    float* ws_s = smf + 64*132;          // 32*132
    float* v_s  = ws_s + 32*132;         // 128
    int*   mk_s = (int*)(v_s + 128);     // 128
    int*   ts_s = mk_s + 128;            // 64
    const int q = blockIdx.x, b = blockIdx.y, th = blockIdx.z;
    const int bq = b*QQ + q;
    const int cnt = g_cnt[bq], off = g_off[bq];
    const int sbase = th * 64;
    const int lc = min(64, cnt - sbase);          // slots this block owns (may be <=0)
    if (th == 1 && lc <= 0) return;
    const int tid = threadIdx.x;
    const int tx = tid & 31, ty = tid >> 5;
    const int chunks = (lc > 0) ? ((lc + 31) >> 5) : 0;   // 0..2

    if (tid < 128) mk_s[tid] = exp_mask[bq*LEN + tid];
    if (tid < 64)  ts_s[tid] = (tid < lc) ? (g_tidx[off + sbase + tid] & (LEN-1)) : 0;
    #pragma unroll
    for (int i = 0; i < 8; i++){
        int idx = tid + i*256;                // 0..2047 = 64 rows x 32 float4
        int t = idx >> 5;
        int a = (idx & 31) * 4;
        float4 val = make_float4(0.f, 0.f, 0.f, 0.f);
        if (t < lc) val = *(const float4*)(g_uhc + (size_t)(off + sbase + t)*AA + a);
        *(float4*)&uh_s[t*132 + a] = val;
    }
    const float* wsg = g_ws + b * PP * AA;
    #pragma unroll
    for (int i = 0; i < 4; i++){
        int idx = tid + i*256;
        int p = idx >> 5;
        int a = (idx & 31) * 4;
        *(float4*)&ws_s[p*132 + a] = *(const float4*)(wsg + p*AA + a);
    }
    if (tid < 32)  *(float4*)&v_s[tid*4] = *(const float4*)(v_w + tid*4);
    __syncthreads();

    const int p0 = ty * 4;
    float acc[4][2];
    #pragma unroll
    for (int i = 0; i < 4; i++)
        #pragma unroll
        for (int j = 0; j < 2; j++) acc[i][j] = 0.0f;

    for (int a0 = 0; a0 < AA; a0 += 4){
        float4 v4 = *(const float4*)&v_s[a0];
        float4 w[4];
        #pragma unroll
        for (int i = 0; i < 4; i++) w[i] = *(const float4*)&ws_s[(p0+i)*132 + a0];
        #pragma unroll
        for (int j = 0; j < 2; j++){
            if (j < chunks){                       // uniform per block
                float4 u = *(const float4*)&uh_s[(tx + 32*j)*132 + a0];
                #pragma unroll
                for (int i = 0; i < 4; i++){
                    float s;
                    s  = tanh_fast(u.x + w[i].x) * v4.x;
                    s += tanh_fast(u.y + w[i].y) * v4.y;
                    s += tanh_fast(u.z + w[i].z) * v4.z;
                    s += tanh_fast(u.w + w[i].w) * v4.w;
                    acc[i][j] += s;
                }
            }
        }
    }
    #pragma unroll
    for (int i = 0; i < 4; i++){
        float* er = g_e + (((size_t)(b*PP + p0 + i))*QQ + q) * LEN;
        if (th == 0){
            #pragma unroll
            for (int j = 0; j < 4; j++){
                int t = tx + 32*j;
                if (!mk_s[t]) er[t] = -1.0e9f;
            }
        }
        #pragma unroll
        for (int j = 0; j < 2; j++){
            if (j < chunks){
                int slot = tx + 32*j;
                if (slot < lc) er[ts_s[slot]] = acc[i][j];
            }
        }
    }
}

// ---------------------------------------------------------------------------
// K4: softmax REDUCE-ONLY: per (b,p) row of 4096, write max and 1/sum.
// ---------------------------------------------------------------------------
__global__ void __launch_bounds__(256) k_redmax(){
    __shared__ float red[8];
    __shared__ float bcast;
    const int bp  = blockIdx.x;
    const float* row = g_e + (size_t)bp * (QQ*LEN);
    const int tid  = threadIdx.x;
    const int lane = tid & 31, warp = tid >> 5;

    float4 v[4];
    #pragma unroll
    for (int i = 0; i < 4; i++) v[i] = *(const float4*)&row[(tid + i*256)*4];

    float mx = -3.0e38f;
    #pragma unroll
    for (int i = 0; i < 4; i++)
        mx = fmaxf(mx, fmaxf(fmaxf(v[i].x, v[i].y), fmaxf(v[i].z, v[i].w)));
    #pragma unroll
    for (int o = 16; o; o >>= 1) mx = fmaxf(mx, __shfl_xor_sync(0xffffffffu, mx, o));
    if (lane == 0) red[warp] = mx;
    __syncthreads();
    if (tid == 0){
        float m = red[0];
        #pragma unroll
        for (int i = 1; i < 8; i++) m = fmaxf(m, red[i]);
        bcast = m;
    }
    __syncthreads();
    mx = bcast;

    float s = 0.0f;
    #pragma unroll
    for (int i = 0; i < 4; i++){
        s += __expf(v[i].x - mx) + __expf(v[i].y - mx)
           + __expf(v[i].z - mx) + __expf(v[i].w - mx);
    }
    #pragma unroll
    for (int o = 16; o; o >>= 1) s += __shfl_xor_sync(0xffffffffu, s, o);
    if (lane == 0) red[warp] = s;
    __syncthreads();
    if (tid == 0){
        float t = 0.0f;
        #pragma unroll
        for (int i = 0; i < 8; i++) t += red[i];
        g_mx[bp]  = mx;
        g_inv[bp] = 1.0f / t;
    }
}

// ---------------------------------------------------------------------------
// K5: out = softmax(e) @ Xh via mma.sync fp16 (unchanged from R11).
// ---------------------------------------------------------------------------
#define XSROW 520
#define XSCH  (32*XSROW*2)
#define ASROW 136
#define KOUT_SMEM (2*XSCH + 2*32*ASROW*2 + 128*4 + 96*4 + 256)

__global__ void __launch_bounds__(256) k_out(const int* __restrict__ req_mask,
                                             float* __restrict__ out){
    extern __shared__ char smc[];
    const uint32_t sb = smem_u32(smc);
    __half* ah_s = (__half*)(smc + 2*XSCH);
    __half* al_s = ah_s + 32*ASROW;
    int*    ts_o = (int*)(al_s + 32*ASROW);
    float*  rm_s = (float*)(ts_o + 128);
    float*  mx_s = rm_s + 32;
    float*  iv_s = mx_s + 32;
    const int q = blockIdx.x, b = blockIdx.y;
    const int tid = threadIdx.x;
    const int lane = tid & 31, wid = tid >> 5;
    const int bq = b*QQ + q;
    const int cnt = g_cnt[bq], off = g_off[bq];
    const int chunks = (cnt + 31) >> 5;

    if (tid < 128) ts_o[tid] = (tid < cnt) ? (g_tidx[off + tid] & (LEN-1)) : 0;
    if (tid < 32){
        rm_s[tid] = (float)req_mask[b*PP + tid];
        mx_s[tid] = g_mx[b*PP + tid];
        iv_s[tid] = g_inv[b*PP + tid];
    }
    __syncthreads();

    #pragma unroll
    for (int i = 0; i < 16; i++){
        int idx = tid + i*256;
        int p = idx >> 7;
        int slot = idx & 127;
        float av = 0.0f;
        if (slot < cnt){
            float raw = g_e[(((size_t)(b*PP + p))*QQ + q)*LEN + ts_o[slot]];
            av = __expf(raw - mx_s[p]) * iv_s[p];
        }
        __half ah = __float2half(av);
        ah_s[p*ASROW + slot] = ah;
        al_s[p*ASROW + slot] = __float2half(av - __half2float(ah));
    }

    {
        #pragma unroll
        for (int i = 0; i < 8; i++){
            int idx = tid + i*256;
            int r = idx >> 6, seg = idx & 63;
            cp16(sb + (uint32_t)r*(XSROW*2) + seg*16,
                 g_Xh + (size_t)(off + r)*DD + seg*8);
        }
        CP_COMMIT();
        CP_WAIT0();
    }
    __syncthreads();

    float acc[2][8][4];
    #pragma unroll
    for (int m = 0; m < 2; m++)
        #pragma unroll
        for (int n = 0; n < 8; n++)
            #pragma unroll
            for (int c = 0; c < 4; c++) acc[m][n][c] = 0.0f;

    const uint32_t aA0 = smem_u32(ah_s) + (uint32_t)(lane & 15)*(ASROW*2) + ((lane >> 4) << 4);
    const uint32_t aA1 = smem_u32(al_s) + (uint32_t)(lane & 15)*(ASROW*2) + ((lane >> 4) << 4);
    const uint32_t bg = lane >> 3;
    const uint32_t bl8 = lane & 7;
    const uint32_t brow = bl8 + ((bg & 1) << 3);
    const uint32_t bcol = (bg >> 1) << 3;
    const uint32_t b_base = (uint32_t)brow*(XSROW*2) + bcol*2 + (uint32_t)wid*128;

    for (int c = 0; c < chunks; c++){
        const uint32_t boff = (uint32_t)(c & 1) * XSCH;
        const uint32_t noff = boff ^ XSCH;
        if (c + 1 < chunks){
            #pragma unroll
            for (int i = 0; i < 8; i++){
                int idx = tid + i*256;
                int r = idx >> 6, seg = idx & 63;
                cp16(sb + noff + (uint32_t)r*(XSROW*2) + seg*16,
                     g_Xh + (size_t)(off + (c+1)*32 + r)*DD + seg*8);
            }
            CP_COMMIT();
        }
        #pragma unroll
        for (int kk = 0; kk < 2; kk++){
            const uint32_t kbA = (uint32_t)(c*32 + kk*16) * 2;
            const uint32_t kbB = (uint32_t)(kk*16)*(XSROW*2);
            uint32_t fah[4], fal[4];
            ldsm4(fah, aA0 + kbA);
            ldsm4(fal, aA1 + kbA);
            uint32_t fah2[4], fal2[4];
            ldsm4(fah2, aA0 + (uint32_t)16*(ASROW*2) + kbA);
            ldsm4(fal2, aA1 + (uint32_t)16*(ASROW*2) + kbA);
            #pragma unroll
            for (int nt4 = 0; nt4 < 4; nt4++){
                uint32_t bt[4];
                ldsm4t(bt, sb + boff + b_base + kbB + (uint32_t)nt4*32);
                uint32_t b0[2] = {bt[0], bt[1]};
                uint32_t b1[2] = {bt[2], bt[3]};
                mma_f16(acc[0][nt4*2],   fah,  b0);
                mma_f16(acc[0][nt4*2],   fal,  b0);
                mma_f16(acc[0][nt4*2+1], fah,  b1);
                mma_f16(acc[0][nt4*2+1], fal,  b1);
                mma_f16(acc[1][nt4*2],   fah2, b0);
                mma_f16(acc[1][nt4*2],   fal2, b0);
                mma_f16(acc[1][nt4*2+1], fah2, b1);
                mma_f16(acc[1][nt4*2+1], fal2, b1);
            }
        }
        if (c + 1 < chunks) CP_WAIT0();
        __syncthreads();
    }

    const int r = lane >> 2, cp2 = (lane & 3) * 2;
    float* og = out + (size_t)bq * PP * DD;
    #pragma unroll
    for (int m = 0; m < 2; m++){
        int pA = m*16 + r, pB = pA + 8;
        float rA = rm_s[pA], rB = rm_s[pB];
        #pragma unroll
        for (int nt = 0; nt < 8; nt++){
            int d = wid*64 + nt*8 + cp2;
            *(float2*)(og + (size_t)pA*DD + d) =
                make_float2(acc[m][nt][0]*rA, acc[m][nt][1]*rA);
            *(float2*)(og + (size_t)pB*DD + d) =
                make_float2(acc[m][nt][2]*rB, acc[m][nt][3]*rB);
        }
    }
}

// ---------------------------------------------------------------------------
extern "C" void kernel_launch(void* const* d_in, const int* in_sizes, int n_in,
                              void* d_out, int out_size){
    const float* exp_tokens = (const float*)d_in[0];
    const int*   exp_mask   = (const int*)  d_in[1];
    const float* s_j        = (const float*)d_in[2];
    const int*   req_mask   = (const int*)  d_in[3];
    const float* Ws_w       = (const float*)d_in[4];
    const float* Ws_b       = (const float*)d_in[5];
    const float* U_w        = (const float*)d_in[6];
    const float* v_w        = (const float*)d_in[7];
    float* out = (float*)d_out;

    const int smem_score = (64*132 + 32*132 + 128)*4 + (128+64)*4;  // 51968 B
    cudaFuncSetAttribute(k_score,  cudaFuncAttributeMaxDynamicSharedMemorySize, smem_score);
    cudaFuncSetAttribute(k_out,    cudaFuncAttributeMaxDynamicSharedMemorySize, KOUT_SMEM);
    cudaFuncSetAttribute(k_uh_mma, cudaFuncAttributeMaxDynamicSharedMemorySize, UHMMA_SMEM);

    k_setup  <<<384, 256>>>(s_j, Ws_w, Ws_b, U_w, exp_mask);
    k_compact<<<NBQ, 256>>>();
    k_uh_mma <<<2*NBQ, 512, UHMMA_SMEM>>>(exp_tokens);
    k_score  <<<dim3(QQ, BB, 2), 256, smem_score>>>(exp_mask, v_w);
    k_redmax <<<BB*PP, 256>>>();
    k_out    <<<dim3(QQ, BB), 256, KOUT_SMEM>>>(req_mask, out);
}

// round 14
// speedup vs baseline: 1.0435x; 1.0435x over previous
#include <cuda_runtime.h>
#include <cuda_bf16.h>
#include <cuda_fp16.h>
#include <cstdint>

#define BB  8
#define QQ  32
#define LEN 128
#define DD  512
#define PP  32
#define AA  128
#define NBQ (BB*QQ)

// Scratch (device globals: allocation-free, graph-capturable)
__device__ float g_ws[BB*PP*AA];                 // (B,P,A)
__device__ __half g_uhc[BB*QQ*LEN*AA];           // compacted uh rows (fp16, 8MB)
__device__ float g_e [BB*PP*QQ*LEN];             // (B,P,Q,LE) raw scores, 4 MB
__device__ float g_mx[BB*PP];                    // softmax row max
__device__ float g_inv[BB*PP];                   // softmax 1/sum
__device__ __half g_Uh[AA*DD];                   // U hi split (fp16)
__device__ __half g_Ul[AA*DD];                   // U lo split (fp16)
__device__ __half g_Xh[(NBQ*LEN + 64)*DD];       // compacted X rows fp16 (32MB)
__device__ int   g_cnt[NBQ];                     // unmasked count per (b,q)
__device__ int   g_off[NBQ+1];                   // exclusive offsets
__device__ int   g_tloc[NBQ*LEN];                // per-bq local compacted t
__device__ int   g_tidx[NBQ*LEN + 128];          // dense flat rows (bq*128+t), padded
__device__ int   g_nblk[1];                      // #128-row blocks

// ---------------------------------------------------------------------------
// helpers
// ---------------------------------------------------------------------------
__device__ __forceinline__ float tanh_fast(float x){
    float y; asm("tanh.approx.f32 %0, %1;" : "=f"(y) : "f"(x)); return y;
}
__device__ __forceinline__ uint32_t smem_u32(const void* p){
    uint32_t a;
    asm("{ .reg .u64 t; cvta.to.shared.u64 t, %1; cvt.u32.u64 %0, t; }" : "=r"(a) : "l"(p));
    return a;
}
__device__ __forceinline__ uint32_t h2u(__half2 v){
    return *reinterpret_cast<uint32_t*>(&v);
}
// sm_80+ primitives (valid at target sm_103)
__device__ __forceinline__ void ldsm4(uint32_t* r, uint32_t a){
    asm volatile("ldmatrix.sync.aligned.m8n8.x4.shared.b16 {%0,%1,%2,%3}, [%4];"
        : "=r"(r[0]), "=r"(r[1]), "=r"(r[2]), "=r"(r[3]) : "r"(a));
}
__device__ __forceinline__ void ldsm4t(uint32_t* r, uint32_t a){
    asm volatile("ldmatrix.sync.aligned.m8n8.x4.trans.shared.b16 {%0,%1,%2,%3}, [%4];"
        : "=r"(r[0]), "=r"(r[1]), "=r"(r[2]), "=r"(r[3]) : "r"(a));
}
__device__ __forceinline__ void mma_f16(float* c, const uint32_t* a, const uint32_t* b){
    asm volatile("mma.sync.aligned.m16n8k16.row.col.f32.f16.f16.f32 "
        "{%0,%1,%2,%3}, {%4,%5,%6,%7}, {%8,%9}, {%0,%1,%2,%3};"
        : "+f"(c[0]), "+f"(c[1]), "+f"(c[2]), "+f"(c[3])
        : "r"(a[0]), "r"(a[1]), "r"(a[2]), "r"(a[3]), "r"(b[0]), "r"(b[1]));
}
__device__ __forceinline__ void cp16(uint32_t d, const void* s){
    asm volatile("cp.async.cg.shared.global [%0], [%1], 16;" :: "r"(d), "l"(s));
}
#define CP_COMMIT() asm volatile("cp.async.commit_group;" ::: "memory")
#define CP_WAIT0()  asm volatile("cp.async.wait_group 0;" ::: "memory")

// ---------------------------------------------------------------------------
// K_SETUP (fused): blocks 0..63 -> ws (4 bp rows each); 64..319 -> compact1;
//                  320..383 -> prep_u
// ---------------------------------------------------------------------------
__global__ void __launch_bounds__(256) k_setup(const float* __restrict__ s_j,
                                               const float* __restrict__ Ws_w,
                                               const float* __restrict__ Ws_b,
                                               const float* __restrict__ U,
                                               const int*   __restrict__ exp_mask){
    const int blk = blockIdx.x;
    const int tid = threadIdx.x;
    if (blk < 64){
        __shared__ float sj[4][DD];
        const int bp0 = blk * 4;
        #pragma unroll
        for (int i = 0; i < 2; i++){
            int idx = tid + i*256;
            int rr = idx >> 7, c4 = (idx & 127) * 4;
            *(float4*)&sj[rr][c4] = *(const float4*)(s_j + (size_t)(bp0+rr)*DD + c4);
        }
        __syncthreads();
        const int a = tid & 127, half = tid >> 7;
        float acc0 = 0.0f, acc1 = 0.0f;
        const float* wr = Ws_w + (size_t)a*DD;
        const float* s0 = sj[half*2 + 0];
        const float* s1 = sj[half*2 + 1];
        #pragma unroll 8
        for (int d = 0; d < DD; d += 4){
            float4 w = *(const float4*)(wr + d);
            float4 x0 = *(const float4*)(s0 + d);
            float4 x1 = *(const float4*)(s1 + d);
            acc0 += w.x*x0.x + w.y*x0.y + w.z*x0.z + w.w*x0.w;
            acc1 += w.x*x1.x + w.y*x1.y + w.z*x1.z + w.w*x1.w;
        }
        float bb = Ws_b[a];
        g_ws[(bp0 + half*2 + 0)*AA + a] = acc0 + bb;
        g_ws[(bp0 + half*2 + 1)*AA + a] = acc1 + bb;
    } else if (blk < 320){
        __shared__ int wc[4];
        const int bq = blk - 64;
        const int lane = tid & 31, w = tid >> 5;
        bool m = false; unsigned bal = 0;
        if (tid < 128){
            m = exp_mask[bq*LEN + tid] != 0;
            bal = __ballot_sync(0xffffffffu, m);
            if (lane == 0) wc[w] = __popc(bal);
        }
        __syncthreads();
        if (tid < 128){
            int base = 0;
            #pragma unroll
            for (int i = 0; i < 4; i++) if (i < w) base += wc[i];
            int pre = __popc(bal & ((1u << lane) - 1u));
            if (m) g_tloc[bq*LEN + base + pre] = tid;
            if (tid == 0) g_cnt[bq] = wc[0] + wc[1] + wc[2] + wc[3];
        }
    } else {
        int idx = ((blk - 320) * 256 + tid) * 4;
        float4 v = *(const float4*)(U + idx);
        __half hx = __float2half(v.x), hy = __float2half(v.y);
        __half hz = __float2half(v.z), hw = __float2half(v.w);
        __half2 h01 = __halves2half2(hx, hy);
        __half2 h23 = __halves2half2(hz, hw);
        __half2 l01 = __floats2half2_rn(v.x - __half2float(hx), v.y - __half2float(hy));
        __half2 l23 = __floats2half2_rn(v.z - __half2float(hz), v.w - __half2float(hw));
        *(__half2*)(g_Uh + idx)     = h01;
        *(__half2*)(g_Uh + idx + 2) = h23;
        *(__half2*)(g_Ul + idx)     = l01;
        *(__half2*)(g_Ul + idx + 2) = l23;
    }
}

// ---------------------------------------------------------------------------
// K_COMPACT: fused scan + scatter. 256 blocks x 256 thr.
// ---------------------------------------------------------------------------
__global__ void __launch_bounds__(256) k_compact(){
    __shared__ int s[256];
    const int bq = blockIdx.x, tid = threadIdx.x;
    s[tid] = g_cnt[tid];
    __syncthreads();
    #pragma unroll
    for (int o = 1; o < 256; o <<= 1){
        int v = (tid >= o) ? s[tid - o] : 0;
        __syncthreads();
        s[tid] += v;
        __syncthreads();
    }
    const int off = (bq == 0) ? 0 : s[bq - 1];
    const int cnt = s[bq] - off;
    if (tid < cnt) g_tidx[off + tid] = bq*LEN + g_tloc[bq*LEN + tid];
    if (tid == 0){ g_off[bq + 1] = s[bq]; if (bq == 0) g_off[0] = 0; }
    if (bq == 0){
        const int tot = s[255];
        const int pad = (tot + 127) & ~127;
        if (tid < pad - tot) g_tidx[tot + tid] = 0;
        if (tid == 0) g_nblk[0] = pad >> 7;
        uint4* z = (uint4*)(g_Xh + (size_t)tot * DD);
        #pragma unroll
        for (int i = 0; i < 8; i++) z[tid + i*256] = make_uint4(0,0,0,0);
    }
}

// ---------------------------------------------------------------------------
// K2: uh = gather(X) @ U^T, fp16 2-term, N-split CTAs; epilogue stores fp16.
// ---------------------------------------------------------------------------
#define XROWB 144
#define XTILEB (128*XROWB)
#define UTILEB (64*XROWB)
#define CHUNKB (XTILEB + 2*UTILEB)
#define UHMMA_SMEM (2*CHUNKB)              // 73728

__global__ void __launch_bounds__(512, 2) k_uh_mma(const float* __restrict__ X){
    const int bid = blockIdx.x;
    if (bid >= 2*g_nblk[0]) return;
    extern __shared__ char sm[];
    const uint32_t sb = smem_u32(sm);
    const int tid  = threadIdx.x;
    const int lane = tid & 31, wid = tid >> 5;
    const int warp_m = wid & 3;
    const int warp_n = wid >> 2;
    const int rb = bid >> 1, nh = bid & 1;
    const int m0 = rb * 128;
    const int ub = nh * 64;

    float acc[2][2][4];
    #pragma unroll
    for (int a = 0; a < 2; a++)
        #pragma unroll
        for (int b = 0; b < 2; b++)
            #pragma unroll
            for (int c = 0; c < 4; c++) acc[a][b][c] = 0.0f;

    const float* xp[4];
    uint32_t soff[4];
    #pragma unroll
    for (int j = 0; j < 4; j++){
        int idx = tid + j*512;
        int row = idx >> 4, k4 = (idx & 15) * 4;
        xp[j] = X + (size_t)g_tidx[m0 + row]*DD + k4;
        soff[j] = (uint32_t)row*XROWB + (uint32_t)k4*2;
    }
    const int urow = tid >> 3, useg = tid & 7;
    const uint32_t uoff = (uint32_t)urow*XROWB + useg*16;

    float4 xr[4];
    #pragma unroll
    for (int j = 0; j < 4; j++) xr[j] = *(const float4*)(xp[j]);
    cp16(sb + XTILEB          + uoff, g_Uh + (size_t)(ub + urow)*DD + useg*8);
    cp16(sb + XTILEB + UTILEB + uoff, g_Ul + (size_t)(ub + urow)*DD + useg*8);
    CP_COMMIT();
    #pragma unroll
    for (int j = 0; j < 4; j++){
        int idx = tid + j*512;
        int row = idx >> 4, k4 = (idx & 15) * 4;
        float4 v = xr[j];
        uint2 h = make_uint2(h2u(__floats2half2_rn(v.x, v.y)),
                             h2u(__floats2half2_rn(v.z, v.w)));
        *(uint2*)(sm + soff[j]) = h;
        if (nh == 0) *(uint2*)(g_Xh + (size_t)(m0 + row)*DD + k4) = h;
    }
    CP_WAIT0();
    __syncthreads();

    const uint32_t a_base = (uint32_t)(warp_m*32 + (lane & 15))*XROWB + ((lane >> 4) << 4);
    const uint32_t b_base = (uint32_t)(warp_n*16 + (lane & 7) + ((lane >> 4) << 3))*XROWB
                          + (((lane >> 3) & 1) << 4);

    for (int c = 0; c < DD/64; c++){
        const uint32_t boff = (uint32_t)(c & 1) * CHUNKB;
        const uint32_t noff = boff ^ CHUNKB;
        const int k0n = (c+1) * 64;
        if (c < 7){
            #pragma unroll
            for (int j = 0; j < 4; j++) xr[j] = *(const float4*)(xp[j] + k0n);
            cp16(sb + noff + XTILEB          + uoff, g_Uh + (size_t)(ub + urow)*DD + k0n + useg*8);
            cp16(sb + noff + XTILEB + UTILEB + uoff, g_Ul + (size_t)(ub + urow)*DD + k0n + useg*8);
            CP_COMMIT();
        }
        const uint32_t xh = sb + boff;
        const uint32_t uh = xh + XTILEB, ul = uh + UTILEB;
        #pragma unroll
        for (int ks = 0; ks < 4; ks++){
            const uint32_t kb = (uint32_t)ks * 32;
            uint32_t ah[2][4];
            ldsm4(ah[0], xh + a_base + kb);
            ldsm4(ah[1], xh + a_base + kb + 16*XROWB);
            uint32_t t0[4], t1[4];
            ldsm4(t0, uh + b_base + kb);
            ldsm4(t1, ul + b_base + kb);
            uint32_t bh0[2] = {t0[0], t0[1]}, bh1[2] = {t0[2], t0[3]};
            uint32_t bl0[2] = {t1[0], t1[1]}, bl1[2] = {t1[2], t1[3]};
            #pragma unroll
            for (int mt = 0; mt < 2; mt++){
                mma_f16(acc[mt][0], ah[mt], bh0);
                mma_f16(acc[mt][0], ah[mt], bl0);
                mma_f16(acc[mt][1], ah[mt], bh1);
                mma_f16(acc[mt][1], ah[mt], bl1);
            }
        }
        if (c < 7){
            #pragma unroll
            for (int j = 0; j < 4; j++){
                int idx = tid + j*512;
                int row = idx >> 4, k4 = (idx & 15) * 4;
                float4 v = xr[j];
                uint2 h = make_uint2(h2u(__floats2half2_rn(v.x, v.y)),
                                     h2u(__floats2half2_rn(v.z, v.w)));
                *(uint2*)(sm + noff + soff[j]) = h;
                if (nh == 0) *(uint2*)(g_Xh + (size_t)(m0 + row)*DD + k0n + k4) = h;
            }
            CP_WAIT0();
        }
        __syncthreads();
    }

    // ---- epilogue: fp16 stores ----
    const int r = lane >> 2, cp2 = (lane & 3) * 2;
    __half* base = g_uhc + (size_t)(m0 + warp_m*32) * AA + ub + warp_n*16;
    #pragma unroll
    for (int mt = 0; mt < 2; mt++){
        #pragma unroll
        for (int nt = 0; nt < 2; nt++){
            __half* p0 = base + (size_t)(mt*16 + r) * AA + nt*8 + cp2;
            __half* p1 = base + (size_t)(mt*16 + r + 8) * AA + nt*8 + cp2;
            *(uint32_t*)p0 = h2u(__floats2half2_rn(acc[mt][nt][0], acc[mt][nt][1]));
            *(uint32_t*)p1 = h2u(__floats2half2_rn(acc[mt][nt][2], acc[mt][nt][3]));
        }
    }
}

// ---------------------------------------------------------------------------
// K3: e over compacted slots (R11 shape, grid (Q,B)); uh_s in fp16 smem.
// smem 52.2KB -> 4 CTAs/SM. Masked t written -1e9 directly.
// ---------------------------------------------------------------------------
__global__ void __launch_bounds__(256, 4) k_score(const int*   __restrict__ exp_mask,
                                                  const float* __restrict__ v_w){
    extern __shared__ float smf[];
    __half* uh_s = (__half*)smf;               // 128 rows x 132 halfs (33792 B)
    float* ws_s = smf + (128*132*2)/4;         // 32*132 f32
    float* v_s  = ws_s + 32*132;               // 128
    int*   mk_s = (int*)(v_s + 128);           // 128
    int*   ts_s = mk_s + 128;                  // 128
    const int q = blockIdx.x, b = blockIdx.y;
    const int tid = threadIdx.x;
    const int tx = tid & 31, ty = tid >> 5;
    const int bq = b*QQ + q;
    const int cnt = g_cnt[bq], off = g_off[bq];
    const int chunks = (cnt + 31) >> 5;

    if (tid < 128){
        mk_s[tid] = exp_mask[bq*LEN + tid];
        ts_s[tid] = (tid < cnt) ? (g_tidx[off + tid] & (LEN-1)) : 0;
    }
    // fill uh_s from fp16 g_uhc: 128 rows x 128 halfs = 2048 uint4
    #pragma unroll
    for (int i = 0; i < 8; i++){
        int idx = tid + i*256;                  // 0..2047
        int t = idx >> 4;                       // row
        int a = (idx & 15) * 8;                 // half index
        uint4 val = make_uint4(0,0,0,0);
        if (t < cnt) val = *(const uint4*)(g_uhc + (size_t)(off + t)*AA + a);
        // smem store as 2x uint2 (row pitch 132 halfs = 264B, 8B aligned)
        uint32_t hoff = (uint32_t)t*132 + (uint32_t)a;
        *(uint2*)&uh_s[hoff]     = make_uint2(val.x, val.y);
        *(uint2*)&uh_s[hoff + 4] = make_uint2(val.z, val.w);
    }
    const float* wsg = g_ws + b * PP * AA;
    #pragma unroll
    for (int i = 0; i < 4; i++){
        int idx = tid + i*256;
        int p = idx >> 5;
        int a = (idx & 31) * 4;
        *(float4*)&ws_s[p*132 + a] = *(const float4*)(wsg + p*AA + a);
    }
    if (tid < 32)  *(float4*)&v_s[tid*4] = *(const float4*)(v_w + tid*4);
    __syncthreads();

    const int p0 = ty * 4;
    float acc[4][4];
    #pragma unroll
    for (int i = 0; i < 4; i++)
        #pragma unroll
        for (int j = 0; j < 4; j++) acc[i][j] = 0.0f;

    for (int a0 = 0; a0 < AA; a0 += 4){
        float4 v4 = *(const float4*)&v_s[a0];
        float4 w[4];
        #pragma unroll
        for (int i = 0; i < 4; i++) w[i] = *(const float4*)&ws_s[(p0+i)*132 + a0];
        #pragma unroll
        for (int j = 0; j < 4; j++){
            if (j < chunks){
                uint2 ud = *(const uint2*)&uh_s[(uint32_t)(tx + 32*j)*132 + a0];
                float2 f0 = __half22float2(*(const __half2*)&ud.x);
                float2 f1 = __half22float2(*(const __half2*)&ud.y);
                #pragma unroll
                for (int i = 0; i < 4; i++){
                    float s;
                    s  = tanh_fast(f0.x + w[i].x) * v4.x;
                    s += tanh_fast(f0.y + w[i].y) * v4.y;
                    s += tanh_fast(f1.x + w[i].z) * v4.z;
                    s += tanh_fast(f1.y + w[i].w) * v4.w;
                    acc[i][j] += s;
                }
            }
        }
    }
    #pragma unroll
    for (int i = 0; i < 4; i++){
        float* er = g_e + (((size_t)(b*PP + p0 + i))*QQ + q) * LEN;
        #pragma unroll
        for (int j = 0; j < 4; j++){
            int t = tx + 32*j;
            if (!mk_s[t]) er[t] = -1.0e9f;
        }
        #pragma unroll
        for (int j = 0; j < 4; j++){
            if (j < chunks){
                int slot = tx + 32*j;
                if (slot < cnt) er[ts_s[slot]] = acc[i][j];
            }
        }
    }
}

// ---------------------------------------------------------------------------
// K4: softmax REDUCE-ONLY: per (b,p) row of 4096, write max and 1/sum.
// ---------------------------------------------------------------------------
__global__ void __launch_bounds__(256) k_redmax(){
    __shared__ float red[8];
    __shared__ float bcast;
    const int bp  = blockIdx.x;
    const float* row = g_e + (size_t)bp * (QQ*LEN);
    const int tid  = threadIdx.x;
    const int lane = tid & 31, warp = tid >> 5;

    float4 v[4];
    #pragma unroll
    for (int i = 0; i < 4; i++) v[i] = *(const float4*)&row[(tid + i*256)*4];

    float mx = -3.0e38f;
    #pragma unroll
    for (int i = 0; i < 4; i++)
        mx = fmaxf(mx, fmaxf(fmaxf(v[i].x, v[i].y), fmaxf(v[i].z, v[i].w)));
    #pragma unroll
    for (int o = 16; o; o >>= 1) mx = fmaxf(mx, __shfl_xor_sync(0xffffffffu, mx, o));
    if (lane == 0) red[warp] = mx;
    __syncthreads();
    if (tid == 0){
        float m = red[0];
        #pragma unroll
        for (int i = 1; i < 8; i++) m = fmaxf(m, red[i]);
        bcast = m;
    }
    __syncthreads();
    mx = bcast;

    float s = 0.0f;
    #pragma unroll
    for (int i = 0; i < 4; i++){
        s += __expf(v[i].x - mx) + __expf(v[i].y - mx)
           + __expf(v[i].z - mx) + __expf(v[i].w - mx);
    }
    #pragma unroll
    for (int o = 16; o; o >>= 1) s += __shfl_xor_sync(0xffffffffu, s, o);
    if (lane == 0) red[warp] = s;
    __syncthreads();
    if (tid == 0){
        float t = 0.0f;
        #pragma unroll
        for (int i = 0; i < 8; i++) t += red[i];
        g_mx[bp]  = mx;
        g_inv[bp] = 1.0f / t;
    }
}

// ---------------------------------------------------------------------------
// K5: out = softmax(e) @ Xh via mma.sync fp16 (unchanged).
// ---------------------------------------------------------------------------
#define XSROW 520
#define XSCH  (32*XSROW*2)
#define ASROW 136
#define KOUT_SMEM (2*XSCH + 2*32*ASROW*2 + 128*4 + 96*4 + 256)

__global__ void __launch_bounds__(256) k_out(const int* __restrict__ req_mask,
                                             float* __restrict__ out){
    extern __shared__ char smc[];
    const uint32_t sb = smem_u32(smc);
    __half* ah_s = (__half*)(smc + 2*XSCH);
    __half* al_s = ah_s + 32*ASROW;
    int*    ts_o = (int*)(al_s + 32*ASROW);
    float*  rm_s = (float*)(ts_o + 128);
    float*  mx_s = rm_s + 32;
    float*  iv_s = mx_s + 32;
    const int q = blockIdx.x, b = blockIdx.y;
    const int tid = threadIdx.x;
    const int lane = tid & 31, wid = tid >> 5;
    const int bq = b*QQ + q;
    const int cnt = g_cnt[bq], off = g_off[bq];
    const int chunks = (cnt + 31) >> 5;

    if (tid < 128) ts_o[tid] = (tid < cnt) ? (g_tidx[off + tid] & (LEN-1)) : 0;
    if (tid < 32){
        rm_s[tid] = (float)req_mask[b*PP + tid];
        mx_s[tid] = g_mx[b*PP + tid];
        iv_s[tid] = g_inv[b*PP + tid];
    }
    __syncthreads();

    #pragma unroll
    for (int i = 0; i < 16; i++){
        int idx = tid + i*256;
        int p = idx >> 7;
        int slot = idx & 127;
        float av = 0.0f;
        if (slot < cnt){
            float raw = g_e[(((size_t)(b*PP + p))*QQ + q)*LEN + ts_o[slot]];
            av = __expf(raw - mx_s[p]) * iv_s[p];
        }
        __half ah = __float2half(av);
        ah_s[p*ASROW + slot] = ah;
        al_s[p*ASROW + slot] = __float2half(av - __half2float(ah));
    }

    {
        #pragma unroll
        for (int i = 0; i < 8; i++){
            int idx = tid + i*256;
            int r = idx >> 6, seg = idx & 63;
            cp16(sb + (uint32_t)r*(XSROW*2) + seg*16,
                 g_Xh + (size_t)(off + r)*DD + seg*8);
        }
        CP_COMMIT();
        CP_WAIT0();
    }
    __syncthreads();

    float acc[2][8][4];
    #pragma unroll
    for (int m = 0; m < 2; m++)
        #pragma unroll
        for (int n = 0; n < 8; n++)
            #pragma unroll
            for (int c = 0; c < 4; c++) acc[m][n][c] = 0.0f;

    const uint32_t aA0 = smem_u32(ah_s) + (uint32_t)(lane & 15)*(ASROW*2) + ((lane >> 4) << 4);
    const uint32_t aA1 = smem_u32(al_s) + (uint32_t)(lane & 15)*(ASROW*2) + ((lane >> 4) << 4);
    const uint32_t bg = lane >> 3;
    const uint32_t bl8 = lane & 7;
    const uint32_t brow = bl8 + ((bg & 1) << 3);
    const uint32_t bcol = (bg >> 1) << 3;
    const uint32_t b_base = (uint32_t)brow*(XSROW*2) + bcol*2 + (uint32_t)wid*128;

    for (int c = 0; c < chunks; c++){
        const uint32_t boff = (uint32_t)(c & 1) * XSCH;
        const uint32_t noff = boff ^ XSCH;
        if (c + 1 < chunks){
            #pragma unroll
            for (int i = 0; i < 8; i++){
                int idx = tid + i*256;
                int r = idx >> 6, seg = idx & 63;
                cp16(sb + noff + (uint32_t)r*(XSROW*2) + seg*16,
                     g_Xh + (size_t)(off + (c+1)*32 + r)*DD + seg*8);
            }
            CP_COMMIT();
        }
        #pragma unroll
        for (int kk = 0; kk < 2; kk++){
            const uint32_t kbA = (uint32_t)(c*32 + kk*16) * 2;
            const uint32_t kbB = (uint32_t)(kk*16)*(XSROW*2);
            uint32_t fah[4], fal[4];
            ldsm4(fah, aA0 + kbA);
            ldsm4(fal, aA1 + kbA);
            uint32_t fah2[4], fal2[4];
            ldsm4(fah2, aA0 + (uint32_t)16*(ASROW*2) + kbA);
            ldsm4(fal2, aA1 + (uint32_t)16*(ASROW*2) + kbA);
            #pragma unroll
            for (int nt4 = 0; nt4 < 4; nt4++){
                uint32_t bt[4];
                ldsm4t(bt, sb + boff + b_base + kbB + (uint32_t)nt4*32);
                uint32_t b0[2] = {bt[0], bt[1]};
                uint32_t b1[2] = {bt[2], bt[3]};
                mma_f16(acc[0][nt4*2],   fah,  b0);
                mma_f16(acc[0][nt4*2],   fal,  b0);
                mma_f16(acc[0][nt4*2+1], fah,  b1);
                mma_f16(acc[0][nt4*2+1], fal,  b1);
                mma_f16(acc[1][nt4*2],   fah2, b0);
                mma_f16(acc[1][nt4*2],   fal2, b0);
                mma_f16(acc[1][nt4*2+1], fah2, b1);
                mma_f16(acc[1][nt4*2+1], fal2, b1);
            }
        }
        if (c + 1 < chunks) CP_WAIT0();
        __syncthreads();
    }

    const int r = lane >> 2, cp2 = (lane & 3) * 2;
    float* og = out + (size_t)bq * PP * DD;
    #pragma unroll
    for (int m = 0; m < 2; m++){
        int pA = m*16 + r, pB = pA + 8;
        float rA = rm_s[pA], rB = rm_s[pB];
        #pragma unroll
        for (int nt = 0; nt < 8; nt++){
            int d = wid*64 + nt*8 + cp2;
            *(float2*)(og + (size_t)pA*DD + d) =
                make_float2(acc[m][nt][0]*rA, acc[m][nt][1]*rA);
            *(float2*)(og + (size_t)pB*DD + d) =
                make_float2(acc[m][nt][2]*rB, acc[m][nt][3]*rB);
        }
    }
}

// ---------------------------------------------------------------------------
extern "C" void kernel_launch(void* const* d_in, const int* in_sizes, int n_in,
                              void* d_out, int out_size){
    const float* exp_tokens = (const float*)d_in[0];
    const int*   exp_mask   = (const int*)  d_in[1];
    const float* s_j        = (const float*)d_in[2];
    const int*   req_mask   = (const int*)  d_in[3];
    const float* Ws_w       = (const float*)d_in[4];
    const float* Ws_b       = (const float*)d_in[5];
    const float* U_w        = (const float*)d_in[6];
    const float* v_w        = (const float*)d_in[7];
    float* out = (float*)d_out;

    const int smem_score = 128*132*2 + 32*132*4 + 128*4 + 128*4 + 128*4;  // 52224 B
    cudaFuncSetAttribute(k_score,  cudaFuncAttributeMaxDynamicSharedMemorySize, smem_score);
    cudaFuncSetAttribute(k_out,    cudaFuncAttributeMaxDynamicSharedMemorySize, KOUT_SMEM);
    cudaFuncSetAttribute(k_uh_mma, cudaFuncAttributeMaxDynamicSharedMemorySize, UHMMA_SMEM);

    k_setup  <<<384, 256>>>(s_j, Ws_w, Ws_b, U_w, exp_mask);
    k_compact<<<NBQ, 256>>>();
    k_uh_mma <<<2*NBQ, 512, UHMMA_SMEM>>>(exp_tokens);
    k_score  <<<dim3(QQ, BB), 256, smem_score>>>(exp_mask, v_w);
    k_redmax <<<BB*PP, 256>>>();
    k_out    <<<dim3(QQ, BB), 256, KOUT_SMEM>>>(req_mask, out);
}